// round 14
// baseline (speedup 1.0000x reference)
#include <cuda_runtime.h>
#include <cuda_fp16.h>
#include <cstdint>

// LightGCN — padded-bucket CSR + fp16 SpMM; half-warp-per-edge inner loop
// (round-12 config), batched-atomic scatter, CAP=128.
// out = [ (ego + e1 + e2 + e3)*0.25 over 151000x64 | user_emb | item_emb ]

#define NU 100000
#define NI 50000
#define NB 1000
#define NN (NU + NI + NB)          // 151000
#define NF2 (NN * 32)              // float2/half2 elems per buffer (dim 64)
#define NF4 (NN * 16)              // float4 elems per buffer
#define CAP 128                    // per-row bucket capacity (max deg ~106)

#define THR 256
#define F4_BLOCKS ((NF4 + THR - 1) / THR)

__device__ __half2 g_h[3][NF2];    // fp16 gather sources: ego, e1, e2
__device__ float2  g_acc[NF2];     // running fp32 sum
__device__ int2    g_edge[(size_t)NN * CAP];  // bucketed (col, val_bits)
__device__ int     g_cnt[NN];      // zero-initialized; re-zeroed by k_spmm<1>

__device__ __forceinline__ unsigned h2_bits(__half2 h) {
    return *reinterpret_cast<unsigned*>(&h);
}
__device__ __forceinline__ __half2 bits_h2(unsigned u) {
    return *reinterpret_cast<__half2*>(&u);
}

// Fused build: blocks [0, F4_BLOCKS) init; the rest bucket-scatter
// (8 edges per thread, batched independent atomics).
__global__ void k_build(const float4* __restrict__ u,
                        const float4* __restrict__ it,
                        const float4* __restrict__ b,
                        float4* __restrict__ out,
                        const int4*   __restrict__ rows4,
                        const int4*   __restrict__ cols4,
                        const float4* __restrict__ vals4,
                        int n_edges) {
    if (blockIdx.x < F4_BLOCKS) {
        int idx = blockIdx.x * THR + threadIdx.x;
        if (idx >= NF4) return;
        float4 v;
        if (idx < NU * 16)              v = u[idx];
        else if (idx < (NU + NI) * 16)  v = it[idx - NU * 16];
        else                            v = b[idx - (NU + NI) * 16];
        ((float4*)g_acc)[idx] = v;
        __half2 h0 = __float22half2_rn(make_float2(v.x, v.y));
        __half2 h1 = __float22half2_rn(make_float2(v.z, v.w));
        ((uint2*)g_h[0])[idx] = make_uint2(h2_bits(h0), h2_bits(h1));
        if (idx < (NU + NI) * 16) __stcs(&out[NF4 + idx], v);
    } else {
        int t = (blockIdx.x - F4_BLOCKS) * THR + threadIdx.x;
        int e0 = t * 8;
        if (e0 >= n_edges) return;
        int4   r0 = __ldcs(rows4 + 2 * t);
        int4   r1 = __ldcs(rows4 + 2 * t + 1);
        int4   c0 = __ldcs(cols4 + 2 * t);
        int4   c1 = __ldcs(cols4 + 2 * t + 1);
        float4 v0 = __ldcs(vals4 + 2 * t);
        float4 v1 = __ldcs(vals4 + 2 * t + 1);
        int rr[8] = {r0.x, r0.y, r0.z, r0.w, r1.x, r1.y, r1.z, r1.w};
        int cc[8] = {c0.x, c0.y, c0.z, c0.w, c1.x, c1.y, c1.z, c1.w};
        float vv[8] = {v0.x, v0.y, v0.z, v0.w, v1.x, v1.y, v1.z, v1.w};
        int n = n_edges - e0;
        if (n >= 8) {
            int pos[8];
            #pragma unroll
            for (int j = 0; j < 8; ++j) pos[j] = atomicAdd(&g_cnt[rr[j]], 1);
            #pragma unroll
            for (int j = 0; j < 8; ++j)
                if (pos[j] < CAP)
                    __stcs(&g_edge[(size_t)rr[j] * CAP + pos[j]],
                           make_int2(cc[j], __float_as_int(vv[j])));
        } else {
            for (int j = 0; j < n; ++j) {
                int pos = atomicAdd(&g_cnt[rr[j]], 1);
                if (pos < CAP)
                    __stcs(&g_edge[(size_t)rr[j] * CAP + pos],
                           make_int2(cc[j], __float_as_int(vv[j])));
            }
        }
    }
}

// SpMM: one warp per node. Half-warp h processes edge 2k+h; each lane covers
// 4 dims (uint2 = 2 half2). Edge list staged in smem, zero-padded to mult of 8.
template <int LAST>
__global__ void __launch_bounds__(256) k_spmm(int src_i, int dst_i,
                                              float4* __restrict__ out) {
    __shared__ int2 sm[8][CAP];              // 1KB per warp
    int wslot = threadIdx.x >> 5;
    int warp = (blockIdx.x * blockDim.x + threadIdx.x) >> 5;
    unsigned lane = threadIdx.x & 31u;
    unsigned half = lane >> 4;               // 0 or 1
    unsigned sub  = lane & 15u;              // dim group
    if (warp >= NN) return;

    int cnt = g_cnt[warp];
    if (cnt > CAP) cnt = CAP;
    int cnt8 = (cnt + 7) & ~7;
    const int4* __restrict__ ep = (const int4*)&g_edge[(size_t)warp * CAP];
    const char* __restrict__ srcb = (const char*)g_h[src_i];

    // stage edges (int4 = 2 edges per load), then zero-pad to cnt8
    int4* sm4 = (int4*)sm[wslot];
    if ((int)lane * 2 < cnt)      sm4[lane]      = __ldcs(&ep[lane]);
    if (64 + (int)lane * 2 < cnt) sm4[32 + lane] = __ldcs(&ep[32 + lane]);
    if ((int)lane < cnt8 - cnt && cnt8 <= CAP)
        sm[wslot][cnt + lane] = make_int2(0, 0);
    __syncwarp();

    float4 acc = make_float4(0.f, 0.f, 0.f, 0.f);

    for (int p = 0; p < cnt8; p += 8) {
        int2 e0 = sm[wslot][p + 0 + half];
        int2 e1 = sm[wslot][p + 2 + half];
        int2 e2 = sm[wslot][p + 4 + half];
        int2 e3 = sm[wslot][p + 6 + half];
        uint2 r0 = __ldg((const uint2*)(srcb + (size_t)(unsigned)e0.x * 128u + sub * 8u));
        uint2 r1 = __ldg((const uint2*)(srcb + (size_t)(unsigned)e1.x * 128u + sub * 8u));
        uint2 r2 = __ldg((const uint2*)(srcb + (size_t)(unsigned)e2.x * 128u + sub * 8u));
        uint2 r3 = __ldg((const uint2*)(srcb + (size_t)(unsigned)e3.x * 128u + sub * 8u));
        float v0 = __int_as_float(e0.y);
        float v1 = __int_as_float(e1.y);
        float v2 = __int_as_float(e2.y);
        float v3 = __int_as_float(e3.y);
        float2 a0 = __half22float2(bits_h2(r0.x)), b0 = __half22float2(bits_h2(r0.y));
        float2 a1 = __half22float2(bits_h2(r1.x)), b1 = __half22float2(bits_h2(r1.y));
        float2 a2 = __half22float2(bits_h2(r2.x)), b2 = __half22float2(bits_h2(r2.y));
        float2 a3 = __half22float2(bits_h2(r3.x)), b3 = __half22float2(bits_h2(r3.y));
        acc.x = fmaf(v0, a0.x, acc.x); acc.y = fmaf(v0, a0.y, acc.y);
        acc.z = fmaf(v0, b0.x, acc.z); acc.w = fmaf(v0, b0.y, acc.w);
        acc.x = fmaf(v1, a1.x, acc.x); acc.y = fmaf(v1, a1.y, acc.y);
        acc.z = fmaf(v1, b1.x, acc.z); acc.w = fmaf(v1, b1.y, acc.w);
        acc.x = fmaf(v2, a2.x, acc.x); acc.y = fmaf(v2, a2.y, acc.y);
        acc.z = fmaf(v2, b2.x, acc.z); acc.w = fmaf(v2, b2.y, acc.w);
        acc.x = fmaf(v3, a3.x, acc.x); acc.y = fmaf(v3, a3.y, acc.y);
        acc.z = fmaf(v3, b3.x, acc.z); acc.w = fmaf(v3, b3.y, acc.w);
    }

    // merge the two half-warp partials (per dim)
    acc.x += __shfl_xor_sync(0xffffffffu, acc.x, 16);
    acc.y += __shfl_xor_sync(0xffffffffu, acc.y, 16);
    acc.z += __shfl_xor_sync(0xffffffffu, acc.z, 16);
    acc.w += __shfl_xor_sync(0xffffffffu, acc.w, 16);

    if (half == 0) {
        unsigned o4 = (unsigned)warp * 16u + sub;     // float4 index
        float4* acc4 = (float4*)g_acc;
        if (LAST) {
            float4 a = __ldcs(&acc4[o4]);
            __stcs(&out[o4], make_float4((a.x + acc.x) * 0.25f,
                                         (a.y + acc.y) * 0.25f,
                                         (a.z + acc.z) * 0.25f,
                                         (a.w + acc.w) * 0.25f));
            if (lane == 0) g_cnt[warp] = 0;           // restore invariant
        } else {
            __half2 h0 = __float22half2_rn(make_float2(acc.x, acc.y));
            __half2 h1 = __float22half2_rn(make_float2(acc.z, acc.w));
            ((uint2*)g_h[dst_i])[o4] = make_uint2(h2_bits(h0), h2_bits(h1));
            float4 a = __ldcs(&acc4[o4]);
            __stcs(&acc4[o4], make_float4(a.x + acc.x, a.y + acc.y,
                                          a.z + acc.z, a.w + acc.w));
        }
    }
}

extern "C" void kernel_launch(void* const* d_in, const int* in_sizes, int n_in,
                              void* d_out, int out_size) {
    const int4*   rows4 = (const int4*)  d_in[0];
    const int4*   cols4 = (const int4*)  d_in[1];
    const float4* vals4 = (const float4*)d_in[2];
    const float4* u     = (const float4*)d_in[3];
    const float4* it    = (const float4*)d_in[4];
    const float4* b     = (const float4*)d_in[5];

    const int n_edges = in_sizes[0];

    int sc_blocks   = ((n_edges + 7) / 8 + THR - 1) / THR;
    int spmm_blocks = (NN * 32 + THR - 1) / THR;

    k_build<<<F4_BLOCKS + sc_blocks, THR>>>(u, it, b, (float4*)d_out,
                                            rows4, cols4, vals4, n_edges);

    k_spmm<0><<<spmm_blocks, THR>>>(0, 1, (float4*)d_out);
    k_spmm<0><<<spmm_blocks, THR>>>(1, 2, (float4*)d_out);
    k_spmm<1><<<spmm_blocks, THR>>>(2, -1, (float4*)d_out);
}

// round 15
// speedup vs baseline: 1.0348x; 1.0348x over previous
#include <cuda_runtime.h>
#include <cuda_fp16.h>
#include <cstdint>

// LightGCN — padded-bucket CSR + fp16 SpMM; half-warp-per-edge inner loop,
// interleaved init/scatter build (2 edges per scatter thread).
// out = [ (ego + e1 + e2 + e3)*0.25 over 151000x64 | user_emb | item_emb ]

#define NU 100000
#define NI 50000
#define NB 1000
#define NN (NU + NI + NB)          // 151000
#define NF2 (NN * 32)              // float2/half2 elems per buffer (dim 64)
#define NF4 (NN * 16)              // float4 elems per buffer
#define CAP 128                    // per-row bucket capacity (max deg ~106)

#define THR 256
#define F4_BLOCKS ((NF4 + THR - 1) / THR)

__device__ __half2 g_h[3][NF2];    // fp16 gather sources: ego, e1, e2
__device__ float2  g_acc[NF2];     // running fp32 sum
__device__ int2    g_edge[(size_t)NN * CAP];  // bucketed (col, val_bits)
__device__ int     g_cnt[NN];      // zero-initialized; re-zeroed by k_spmm<1>

__device__ __forceinline__ unsigned h2_bits(__half2 h) {
    return *reinterpret_cast<unsigned*>(&h);
}
__device__ __forceinline__ __half2 bits_h2(unsigned u) {
    return *reinterpret_cast<__half2*>(&u);
}

// Interleaved build: blocks with bid%3==0 do init; the rest bucket-scatter
// (2 edges per thread for maximum thread-level atomic parallelism).
__global__ void k_build(const float4* __restrict__ u,
                        const float4* __restrict__ it,
                        const float4* __restrict__ b,
                        float4* __restrict__ out,
                        const int2*   __restrict__ rows2,
                        const int2*   __restrict__ cols2,
                        const float2* __restrict__ vals2,
                        int n_edges) {
    int bid = blockIdx.x;
    if (bid % 3 == 0) {
        // ---- init role ----
        int idx = (bid / 3) * THR + threadIdx.x;
        if (idx >= NF4) return;
        float4 v;
        if (idx < NU * 16)              v = u[idx];
        else if (idx < (NU + NI) * 16)  v = it[idx - NU * 16];
        else                            v = b[idx - (NU + NI) * 16];
        ((float4*)g_acc)[idx] = v;
        __half2 h0 = __float22half2_rn(make_float2(v.x, v.y));
        __half2 h1 = __float22half2_rn(make_float2(v.z, v.w));
        ((uint2*)g_h[0])[idx] = make_uint2(h2_bits(h0), h2_bits(h1));
        if (idx < (NU + NI) * 16) __stcs(&out[NF4 + idx], v);
    } else {
        // ---- scatter role: 2 edges per thread ----
        int sb = bid - bid / 3 - 1;
        int t = sb * THR + threadIdx.x;
        int e0 = t * 2;
        if (e0 >= n_edges) return;
        int2   r = __ldcs(rows2 + t);
        int2   c = __ldcs(cols2 + t);
        float2 v = __ldcs(vals2 + t);
        int p0 = atomicAdd(&g_cnt[r.x], 1);
        if (e0 + 1 < n_edges) {
            int p1 = atomicAdd(&g_cnt[r.y], 1);
            if (p0 < CAP)
                __stcs(&g_edge[(size_t)r.x * CAP + p0],
                       make_int2(c.x, __float_as_int(v.x)));
            if (p1 < CAP)
                __stcs(&g_edge[(size_t)r.y * CAP + p1],
                       make_int2(c.y, __float_as_int(v.y)));
        } else {
            if (p0 < CAP)
                __stcs(&g_edge[(size_t)r.x * CAP + p0],
                       make_int2(c.x, __float_as_int(v.x)));
        }
    }
}

// SpMM: one warp per node. Half-warp h processes edge 2k+h; each lane covers
// 4 dims (uint2 = 2 half2). Edge list staged in smem, zero-padded to mult of 8.
template <int LAST>
__global__ void __launch_bounds__(256) k_spmm(int src_i, int dst_i,
                                              float4* __restrict__ out) {
    __shared__ int2 sm[8][CAP];              // 1KB per warp
    int wslot = threadIdx.x >> 5;
    int warp = (blockIdx.x * blockDim.x + threadIdx.x) >> 5;
    unsigned lane = threadIdx.x & 31u;
    unsigned half = lane >> 4;               // 0 or 1
    unsigned sub  = lane & 15u;              // dim group
    if (warp >= NN) return;

    int cnt = g_cnt[warp];
    if (cnt > CAP) cnt = CAP;
    int cnt8 = (cnt + 7) & ~7;
    const int4* __restrict__ ep = (const int4*)&g_edge[(size_t)warp * CAP];
    const char* __restrict__ srcb = (const char*)g_h[src_i];

    // stage edges (int4 = 2 edges per load), then zero-pad to cnt8
    int4* sm4 = (int4*)sm[wslot];
    if ((int)lane * 2 < cnt)      sm4[lane]      = __ldcs(&ep[lane]);
    if (64 + (int)lane * 2 < cnt) sm4[32 + lane] = __ldcs(&ep[32 + lane]);
    if ((int)lane < cnt8 - cnt && cnt8 <= CAP)
        sm[wslot][cnt + lane] = make_int2(0, 0);
    __syncwarp();

    float4 acc = make_float4(0.f, 0.f, 0.f, 0.f);

    for (int p = 0; p < cnt8; p += 8) {
        int2 e0 = sm[wslot][p + 0 + half];
        int2 e1 = sm[wslot][p + 2 + half];
        int2 e2 = sm[wslot][p + 4 + half];
        int2 e3 = sm[wslot][p + 6 + half];
        uint2 r0 = __ldg((const uint2*)(srcb + (size_t)(unsigned)e0.x * 128u + sub * 8u));
        uint2 r1 = __ldg((const uint2*)(srcb + (size_t)(unsigned)e1.x * 128u + sub * 8u));
        uint2 r2 = __ldg((const uint2*)(srcb + (size_t)(unsigned)e2.x * 128u + sub * 8u));
        uint2 r3 = __ldg((const uint2*)(srcb + (size_t)(unsigned)e3.x * 128u + sub * 8u));
        float v0 = __int_as_float(e0.y);
        float v1 = __int_as_float(e1.y);
        float v2 = __int_as_float(e2.y);
        float v3 = __int_as_float(e3.y);
        float2 a0 = __half22float2(bits_h2(r0.x)), b0 = __half22float2(bits_h2(r0.y));
        float2 a1 = __half22float2(bits_h2(r1.x)), b1 = __half22float2(bits_h2(r1.y));
        float2 a2 = __half22float2(bits_h2(r2.x)), b2 = __half22float2(bits_h2(r2.y));
        float2 a3 = __half22float2(bits_h2(r3.x)), b3 = __half22float2(bits_h2(r3.y));
        acc.x = fmaf(v0, a0.x, acc.x); acc.y = fmaf(v0, a0.y, acc.y);
        acc.z = fmaf(v0, b0.x, acc.z); acc.w = fmaf(v0, b0.y, acc.w);
        acc.x = fmaf(v1, a1.x, acc.x); acc.y = fmaf(v1, a1.y, acc.y);
        acc.z = fmaf(v1, b1.x, acc.z); acc.w = fmaf(v1, b1.y, acc.w);
        acc.x = fmaf(v2, a2.x, acc.x); acc.y = fmaf(v2, a2.y, acc.y);
        acc.z = fmaf(v2, b2.x, acc.z); acc.w = fmaf(v2, b2.y, acc.w);
        acc.x = fmaf(v3, a3.x, acc.x); acc.y = fmaf(v3, a3.y, acc.y);
        acc.z = fmaf(v3, b3.x, acc.z); acc.w = fmaf(v3, b3.y, acc.w);
    }

    // merge the two half-warp partials (per dim)
    acc.x += __shfl_xor_sync(0xffffffffu, acc.x, 16);
    acc.y += __shfl_xor_sync(0xffffffffu, acc.y, 16);
    acc.z += __shfl_xor_sync(0xffffffffu, acc.z, 16);
    acc.w += __shfl_xor_sync(0xffffffffu, acc.w, 16);

    if (half == 0) {
        unsigned o4 = (unsigned)warp * 16u + sub;     // float4 index
        float4* acc4 = (float4*)g_acc;
        if (LAST) {
            float4 a = __ldcs(&acc4[o4]);
            __stcs(&out[o4], make_float4((a.x + acc.x) * 0.25f,
                                         (a.y + acc.y) * 0.25f,
                                         (a.z + acc.z) * 0.25f,
                                         (a.w + acc.w) * 0.25f));
            if (lane == 0) g_cnt[warp] = 0;           // restore invariant
        } else {
            __half2 h0 = __float22half2_rn(make_float2(acc.x, acc.y));
            __half2 h1 = __float22half2_rn(make_float2(acc.z, acc.w));
            ((uint2*)g_h[dst_i])[o4] = make_uint2(h2_bits(h0), h2_bits(h1));
            float4 a = __ldcs(&acc4[o4]);
            __stcs(&acc4[o4], make_float4(a.x + acc.x, a.y + acc.y,
                                          a.z + acc.z, a.w + acc.w));
        }
    }
}

extern "C" void kernel_launch(void* const* d_in, const int* in_sizes, int n_in,
                              void* d_out, int out_size) {
    const int2*   rows2 = (const int2*)  d_in[0];
    const int2*   cols2 = (const int2*)  d_in[1];
    const float2* vals2 = (const float2*)d_in[2];
    const float4* u     = (const float4*)d_in[3];
    const float4* it    = (const float4*)d_in[4];
    const float4* b     = (const float4*)d_in[5];

    const int n_edges = in_sizes[0];

    int sc_blocks = ((n_edges + 1) / 2 + THR - 1) / THR;
    // grid so that ceil(grid/3) >= F4_BLOCKS and grid - ceil(grid/3) >= sc_blocks
    int grid = 3 * F4_BLOCKS;
    int need = (3 * sc_blocks) / 2 + 2;
    if (need > grid) grid = need;

    int spmm_blocks = (NN * 32 + THR - 1) / THR;

    k_build<<<grid, THR>>>(u, it, b, (float4*)d_out,
                           rows2, cols2, vals2, n_edges);

    k_spmm<0><<<spmm_blocks, THR>>>(0, 1, (float4*)d_out);
    k_spmm<0><<<spmm_blocks, THR>>>(1, 2, (float4*)d_out);
    k_spmm<1><<<spmm_blocks, THR>>>(2, -1, (float4*)d_out);
}

// round 16
// speedup vs baseline: 1.0928x; 1.0561x over previous
#include <cuda_runtime.h>
#include <cuda_fp16.h>
#include <cstdint>

// LightGCN — padded-bucket CSR + fp16 SpMM; half-warp-per-edge inner loop,
// interleaved init/scatter build (1 edge per scatter thread),
// pre-shifted column byte-offsets in the edge records.
// out = [ (ego + e1 + e2 + e3)*0.25 over 151000x64 | user_emb | item_emb ]

#define NU 100000
#define NI 50000
#define NB 1000
#define NN (NU + NI + NB)          // 151000
#define NF2 (NN * 32)              // float2/half2 elems per buffer (dim 64)
#define NF4 (NN * 16)              // float4 elems per buffer
#define CAP 128                    // per-row bucket capacity (max deg ~106)

#define THR 256
#define F4_BLOCKS ((NF4 + THR - 1) / THR)

__device__ __half2 g_h[3][NF2];    // fp16 gather sources: ego, e1, e2
__device__ float2  g_acc[NF2];     // running fp32 sum
__device__ int2    g_edge[(size_t)NN * CAP];  // bucketed (col*128, val_bits)
__device__ int     g_cnt[NN];      // zero-initialized; re-zeroed by k_spmm<1>

__device__ __forceinline__ unsigned h2_bits(__half2 h) {
    return *reinterpret_cast<unsigned*>(&h);
}
__device__ __forceinline__ __half2 bits_h2(unsigned u) {
    return *reinterpret_cast<__half2*>(&u);
}

// Interleaved build: blocks with bid%5==0 do init; the rest bucket-scatter
// (1 edge per thread: maximum thread-level atomic parallelism).
__global__ void k_build(const float4* __restrict__ u,
                        const float4* __restrict__ it,
                        const float4* __restrict__ b,
                        float4* __restrict__ out,
                        const int*   __restrict__ rows,
                        const int*   __restrict__ cols,
                        const float* __restrict__ vals,
                        int n_edges) {
    int bid = blockIdx.x;
    if (bid % 5 == 0) {
        // ---- init role ----
        int idx = (bid / 5) * THR + threadIdx.x;
        if (idx >= NF4) return;
        float4 v;
        if (idx < NU * 16)              v = u[idx];
        else if (idx < (NU + NI) * 16)  v = it[idx - NU * 16];
        else                            v = b[idx - (NU + NI) * 16];
        ((float4*)g_acc)[idx] = v;
        __half2 h0 = __float22half2_rn(make_float2(v.x, v.y));
        __half2 h1 = __float22half2_rn(make_float2(v.z, v.w));
        ((uint2*)g_h[0])[idx] = make_uint2(h2_bits(h0), h2_bits(h1));
        if (idx < (NU + NI) * 16) __stcs(&out[NF4 + idx], v);
    } else {
        // ---- scatter role: 1 edge per thread ----
        int sb = bid - bid / 5 - 1;
        int t = sb * THR + threadIdx.x;
        if (t >= n_edges) return;
        int   r = __ldcs(rows + t);
        int   c = __ldcs(cols + t);
        float v = __ldcs(vals + t);
        int pos = atomicAdd(&g_cnt[r], 1);
        if (pos < CAP)
            __stcs(&g_edge[(size_t)r * CAP + pos],
                   make_int2(c << 7, __float_as_int(v)));   // byte offset
    }
}

// SpMM: one warp per node. Half-warp h processes edge 2k+h; each lane covers
// 4 dims (uint2 = 2 half2). Edge list staged in smem, zero-padded to mult of 8.
// Edge .x is a pre-shifted byte offset (col*128).
template <int LAST>
__global__ void __launch_bounds__(256) k_spmm(int src_i, int dst_i,
                                              float4* __restrict__ out) {
    __shared__ int2 sm[8][CAP];              // 1KB per warp
    int wslot = threadIdx.x >> 5;
    int warp = (blockIdx.x * blockDim.x + threadIdx.x) >> 5;
    unsigned lane = threadIdx.x & 31u;
    unsigned half = lane >> 4;               // 0 or 1
    unsigned sub  = lane & 15u;              // dim group
    unsigned sub8 = sub * 8u;                // byte offset within row
    if (warp >= NN) return;

    int cnt = g_cnt[warp];
    if (cnt > CAP) cnt = CAP;
    int cnt8 = (cnt + 7) & ~7;
    const int4* __restrict__ ep = (const int4*)&g_edge[(size_t)warp * CAP];
    const char* __restrict__ srcb = (const char*)g_h[src_i];

    // stage edges (int4 = 2 edges per load), then zero-pad to cnt8
    int4* sm4 = (int4*)sm[wslot];
    if ((int)lane * 2 < cnt)      sm4[lane]      = __ldcs(&ep[lane]);
    if (64 + (int)lane * 2 < cnt) sm4[32 + lane] = __ldcs(&ep[32 + lane]);
    if ((int)lane < cnt8 - cnt && cnt8 <= CAP)
        sm[wslot][cnt + lane] = make_int2(0, 0);
    __syncwarp();

    float4 acc = make_float4(0.f, 0.f, 0.f, 0.f);

    for (int p = 0; p < cnt8; p += 8) {
        int2 e0 = sm[wslot][p + 0 + half];
        int2 e1 = sm[wslot][p + 2 + half];
        int2 e2 = sm[wslot][p + 4 + half];
        int2 e3 = sm[wslot][p + 6 + half];
        uint2 r0 = __ldg((const uint2*)(srcb + ((unsigned)e0.x + sub8)));
        uint2 r1 = __ldg((const uint2*)(srcb + ((unsigned)e1.x + sub8)));
        uint2 r2 = __ldg((const uint2*)(srcb + ((unsigned)e2.x + sub8)));
        uint2 r3 = __ldg((const uint2*)(srcb + ((unsigned)e3.x + sub8)));
        float v0 = __int_as_float(e0.y);
        float v1 = __int_as_float(e1.y);
        float v2 = __int_as_float(e2.y);
        float v3 = __int_as_float(e3.y);
        float2 a0 = __half22float2(bits_h2(r0.x)), b0 = __half22float2(bits_h2(r0.y));
        float2 a1 = __half22float2(bits_h2(r1.x)), b1 = __half22float2(bits_h2(r1.y));
        float2 a2 = __half22float2(bits_h2(r2.x)), b2 = __half22float2(bits_h2(r2.y));
        float2 a3 = __half22float2(bits_h2(r3.x)), b3 = __half22float2(bits_h2(r3.y));
        acc.x = fmaf(v0, a0.x, acc.x); acc.y = fmaf(v0, a0.y, acc.y);
        acc.z = fmaf(v0, b0.x, acc.z); acc.w = fmaf(v0, b0.y, acc.w);
        acc.x = fmaf(v1, a1.x, acc.x); acc.y = fmaf(v1, a1.y, acc.y);
        acc.z = fmaf(v1, b1.x, acc.z); acc.w = fmaf(v1, b1.y, acc.w);
        acc.x = fmaf(v2, a2.x, acc.x); acc.y = fmaf(v2, a2.y, acc.y);
        acc.z = fmaf(v2, b2.x, acc.z); acc.w = fmaf(v2, b2.y, acc.w);
        acc.x = fmaf(v3, a3.x, acc.x); acc.y = fmaf(v3, a3.y, acc.y);
        acc.z = fmaf(v3, b3.x, acc.z); acc.w = fmaf(v3, b3.y, acc.w);
    }

    // merge the two half-warp partials (per dim)
    acc.x += __shfl_xor_sync(0xffffffffu, acc.x, 16);
    acc.y += __shfl_xor_sync(0xffffffffu, acc.y, 16);
    acc.z += __shfl_xor_sync(0xffffffffu, acc.z, 16);
    acc.w += __shfl_xor_sync(0xffffffffu, acc.w, 16);

    if (half == 0) {
        unsigned o4 = (unsigned)warp * 16u + sub;     // float4 index
        float4* acc4 = (float4*)g_acc;
        if (LAST) {
            float4 a = __ldcs(&acc4[o4]);
            __stcs(&out[o4], make_float4((a.x + acc.x) * 0.25f,
                                         (a.y + acc.y) * 0.25f,
                                         (a.z + acc.z) * 0.25f,
                                         (a.w + acc.w) * 0.25f));
            if (lane == 0) g_cnt[warp] = 0;           // restore invariant
        } else {
            __half2 h0 = __float22half2_rn(make_float2(acc.x, acc.y));
            __half2 h1 = __float22half2_rn(make_float2(acc.z, acc.w));
            ((uint2*)g_h[dst_i])[o4] = make_uint2(h2_bits(h0), h2_bits(h1));
            float4 a = __ldcs(&acc4[o4]);
            __stcs(&acc4[o4], make_float4(a.x + acc.x, a.y + acc.y,
                                          a.z + acc.z, a.w + acc.w));
        }
    }
}

extern "C" void kernel_launch(void* const* d_in, const int* in_sizes, int n_in,
                              void* d_out, int out_size) {
    const int*    rows = (const int*)   d_in[0];
    const int*    cols = (const int*)   d_in[1];
    const float*  vals = (const float*) d_in[2];
    const float4* u    = (const float4*)d_in[3];
    const float4* it   = (const float4*)d_in[4];
    const float4* b    = (const float4*)d_in[5];

    const int n_edges = in_sizes[0];

    int sc_blocks = (n_edges + THR - 1) / THR;
    // grid sized so ceil(grid/5) >= F4_BLOCKS and grid - ceil(grid/5) >= sc_blocks
    int grid = 5 * F4_BLOCKS;
    int need = (5 * sc_blocks + 3) / 4 + 1;
    if (need > grid) grid = need;

    int spmm_blocks = (NN * 32 + THR - 1) / THR;

    k_build<<<grid, THR>>>(u, it, b, (float4*)d_out, rows, cols, vals, n_edges);

    k_spmm<0><<<spmm_blocks, THR>>>(0, 1, (float4*)d_out);
    k_spmm<0><<<spmm_blocks, THR>>>(1, 2, (float4*)d_out);
    k_spmm<1><<<spmm_blocks, THR>>>(2, -1, (float4*)d_out);
}